// round 2
// baseline (speedup 1.0000x reference)
#include <cuda_runtime.h>
#include <math.h>

// SpectralEMA. Key identities:
//   state_t = a*|state_{t-1}|*unit(x_t) + (1-rho)*x_t
//           = x_t * z_t / w_t,   z_t = a*m_{t-1} + omr*w_t,  m_t = |z_t|
// For real a (theta=0): m_t = rho*m_{t-1} + omr*w_t  -- an AFFINE scan.
// Affine scans compose: over a segment of L steps, m_out = rho^L * m_in + C.
// Phase 1: G parallel segments per (b,f) compute C (and last-step x info).
// Phase 2: combine G segments, reconstruct final complex state from x_last.

#define G 2
#define MAX_BF (32 * 4096)
#define UNR 4

__device__ float g_C[G * MAX_BF];
__device__ float g_lxr[MAX_BF];
__device__ float g_lxi[MAX_BF];
__device__ float g_wl[MAX_BF];

__device__ __forceinline__ float sigmoidf_(float x) {
    return 1.0f / (1.0f + expf(-x));
}

// ---------------- Phase 1: per-segment affine coefficient C ----------------
__global__ __launch_bounds__(256)
void phase1_kernel(const float* __restrict__ fr, const float* __restrict__ fi,
                   const float* __restrict__ rho_logit,
                   int S, int F, int L)
{
    int f = blockIdx.x * blockDim.x + threadIdx.x;
    if (f >= F) return;
    int b = blockIdx.y;
    int g = blockIdx.z;

    float rho = sigmoidf_(rho_logit[f]);
    float omr = 1.0f - rho;

    size_t bf   = (size_t)b * (size_t)F + (size_t)f;
    size_t base = ((size_t)b * (size_t)S + (size_t)g * (size_t)L) * (size_t)F + (size_t)f;
    const float* pr  = fr + base;
    const float* pim = fi + base;
    size_t stF = (size_t)F;

    float C = 0.0f;
    float lxr = 0.0f, lxi = 0.0f, lw = 1.0f;

    int nch = L / UNR;
    float cxr[UNR], cxi[UNR];
#pragma unroll
    for (int k = 0; k < UNR; ++k) {
        cxr[k] = __ldcs(pr  + (size_t)k * stF);
        cxi[k] = __ldcs(pim + (size_t)k * stF);
    }
    pr  += (size_t)UNR * stF;
    pim += (size_t)UNR * stF;

#pragma unroll 1
    for (int j = 0; j < nch; ++j) {
        float nxr[UNR], nxi[UNR];
        if (j + 1 < nch) {
#pragma unroll
            for (int k = 0; k < UNR; ++k) {
                nxr[k] = __ldcs(pr  + (size_t)k * stF);
                nxi[k] = __ldcs(pim + (size_t)k * stF);
            }
            pr  += (size_t)UNR * stF;
            pim += (size_t)UNR * stF;
        }
#pragma unroll
        for (int k = 0; k < UNR; ++k) {
            float xr = cxr[k], xi = cxi[k];
            float x2 = fmaf(xr, xr, xi * xi);
            x2 = fmaxf(x2, 1e-37f);
            float w = sqrtf(x2);
            C = fmaf(rho, C, omr * w);
            lxr = xr; lxi = xi; lw = w;
        }
#pragma unroll
        for (int k = 0; k < UNR; ++k) { cxr[k] = nxr[k]; cxi[k] = nxi[k]; }
    }

    g_C[(size_t)g * MAX_BF + bf] = C;
    if (g == G - 1) {
        g_lxr[bf] = lxr;
        g_lxi[bf] = lxi;
        g_wl[bf]  = lw;
    }
}

// ---------------- Phase 2: combine segments, write output ----------------
__global__ __launch_bounds__(256)
void phase2_kernel(const float* __restrict__ fr, const float* __restrict__ fi,
                   const float* __restrict__ ir, const float* __restrict__ ii,
                   const float* __restrict__ rho_logit,
                   const float* __restrict__ theta_raw,
                   float2* __restrict__ out, int S, int F, int L)
{
    int f = blockIdx.x * blockDim.x + threadIdx.x;
    if (f >= F) return;
    int b = blockIdx.y;
    size_t bf = (size_t)b * (size_t)F + (size_t)f;

    float rho = sigmoidf_(rho_logit[f]);
    float th  = 3.14159265358979323846f * tanhf(theta_raw[f]);
    float ss, sc;
    sincosf(th, &ss, &sc);
    float ar  = rho * sc;
    float ai  = rho * ss;
    float omr = 1.0f - rho;

    // m0 = |init_state|
    float m;
    {
        float sr = ir[bf], si = ii[bf];
        float s2 = fmaf(sr, sr, si * si);
        s2 = fmaxf(s2, 1e-37f);
        m = sqrtf(s2);
    }

    if (ai == 0.0f) {
        // fast path: combine G affine segments
        float D = __powf(rho, (float)L);
#pragma unroll
        for (int g = 0; g < G; ++g)
            m = fmaf(D, m, g_C[(size_t)g * MAX_BF + bf]);
        // m == z_last (real, >= 0).  out = x_last * m / w_last
        float rinv = __frcp_rn(g_wl[bf]);
        float s = m * rinv;
        out[bf] = make_float2(g_lxr[bf] * s, g_lxi[bf] * s);
    } else {
        // general complex-a path (not taken for this dataset): full scan
        const float* pr  = fr + (size_t)b * (size_t)S * (size_t)F + (size_t)f;
        const float* pim = fi + (size_t)b * (size_t)S * (size_t)F + (size_t)f;
        float zr = 0.0f, zi = 0.0f, rinv = 1.0f, lxr = 0.0f, lxi = 0.0f;
        for (int s = 0; s < S; ++s) {
            float xr = __ldcs(pr), xi = __ldcs(pim);
            pr += F; pim += F;
            float x2 = fmaf(xr, xr, xi * xi);
            x2 = fmaxf(x2, 1e-37f);
            float rv = rsqrtf(x2);
            float w  = x2 * rv;
            zr = fmaf(ar, m, omr * w);
            zi = ai * m;
            float z2 = fmaf(zr, zr, zi * zi);
            z2 = fmaxf(z2, 1e-37f);
            m = z2 * rsqrtf(z2);
            rinv = rv; lxr = xr; lxi = xi;
        }
        float outr = (zr * lxr - zi * lxi) * rinv;
        float outi = fmaf(zr, lxi, zi * lxr) * rinv;
        out[bf] = make_float2(outr, outi);
    }
}

// ---------------- Monolithic fallback (unexpected shapes) ----------------
__global__ __launch_bounds__(256)
void mono_kernel(const float* __restrict__ fr, const float* __restrict__ fi,
                 const float* __restrict__ ir, const float* __restrict__ ii,
                 const float* __restrict__ rho_logit,
                 const float* __restrict__ theta_raw,
                 float2* __restrict__ out, int S, int F)
{
    int f = blockIdx.x * blockDim.x + threadIdx.x;
    if (f >= F) return;
    int b = blockIdx.y;
    size_t bf = (size_t)b * (size_t)F + (size_t)f;

    float rho = sigmoidf_(rho_logit[f]);
    float th  = 3.14159265358979323846f * tanhf(theta_raw[f]);
    float ss, sc;
    sincosf(th, &ss, &sc);
    float ar  = rho * sc;
    float ai  = rho * ss;
    float omr = 1.0f - rho;

    float m;
    {
        float sr = ir[bf], si = ii[bf];
        float s2 = fmaf(sr, sr, si * si);
        s2 = fmaxf(s2, 1e-37f);
        m = sqrtf(s2);
    }

    const float* pr  = fr + (size_t)b * (size_t)S * (size_t)F + (size_t)f;
    const float* pim = fi + (size_t)b * (size_t)S * (size_t)F + (size_t)f;
    float zr = 0.0f, zi = 0.0f, rinv = 1.0f, lxr = 0.0f, lxi = 0.0f;
    for (int s = 0; s < S; ++s) {
        float xr = __ldcs(pr), xi = __ldcs(pim);
        pr += F; pim += F;
        float x2 = fmaf(xr, xr, xi * xi);
        x2 = fmaxf(x2, 1e-37f);
        float rv = rsqrtf(x2);
        float w  = x2 * rv;
        zr = fmaf(ar, m, omr * w);
        zi = ai * m;
        float z2 = fmaf(zr, zr, zi * zi);
        z2 = fmaxf(z2, 1e-37f);
        m = z2 * rsqrtf(z2);
        rinv = rv; lxr = xr; lxi = xi;
    }
    float outr = (zr * lxr - zi * lxi) * rinv;
    float outi = fmaf(zr, lxi, zi * lxr) * rinv;
    out[bf] = make_float2(outr, outi);
}

extern "C" void kernel_launch(void* const* d_in, const int* in_sizes, int n_in,
                              void* d_out, int out_size)
{
    const float* fr  = (const float*)d_in[0];   // fft_real  [B,S,F]
    const float* fi  = (const float*)d_in[1];   // fft_imag  [B,S,F]
    const float* ir  = (const float*)d_in[2];   // init_real [B,F]
    const float* ii  = (const float*)d_in[3];   // init_imag [B,F]
    const float* rl  = (const float*)d_in[4];   // rho_logit [F]
    const float* tr  = (const float*)d_in[5];   // theta_raw [F]

    int F  = in_sizes[4];
    int BF = in_sizes[2];
    int B  = BF / F;
    int S  = in_sizes[0] / BF;

    dim3 block(256);

    if (BF <= MAX_BF && (S % (G * UNR)) == 0) {
        int L = S / G;
        dim3 grid1((F + 255) / 256, B, G);
        phase1_kernel<<<grid1, block>>>(fr, fi, rl, S, F, L);
        dim3 grid2((F + 255) / 256, B);
        phase2_kernel<<<grid2, block>>>(fr, fi, ir, ii, rl, tr,
                                        (float2*)d_out, S, F, L);
    } else {
        dim3 grid((F + 255) / 256, B);
        mono_kernel<<<grid, block>>>(fr, fi, ir, ii, rl, tr,
                                     (float2*)d_out, S, F);
    }
}

// round 3
// speedup vs baseline: 1.3543x; 1.3543x over previous
#include <cuda_runtime.h>
#include <math.h>

// SpectralEMA.  state_t = a*|state_{t-1}|*unit(x_t) + (1-rho)*x_t
//             = x_t * z_t / w_t,  z_t = a*m_{t-1} + omr*w_t,  m_t = |z_t|
// Real a (theta=0): m_t = rho*m_{t-1} + omr*w_t  -> affine scan, segments
// compose: m_out = rho^L * m_in + C_seg.
// Phase 1: G parallel segments per chain compute C (float2 = 2 features/thread).
// Phase 2: combine segments, reconstruct final state from last x.

#define G   16
#define UNR 4
#define MAX_BF (32 * 4096)

__device__ float  g_C[G * MAX_BF];
__device__ float2 g_lx[MAX_BF];

__device__ __forceinline__ float sigmoidf_(float x) {
    return 1.0f / (1.0f + expf(-x));
}

// ---------------- Phase 1 ----------------
__global__ __launch_bounds__(256)
void phase1_kernel(const float* __restrict__ fr, const float* __restrict__ fi,
                   const float* __restrict__ rho_logit,
                   int S, int F, int L)
{
    int F2 = F >> 1;
    int f2 = blockIdx.x * blockDim.x + threadIdx.x;
    if (f2 >= F2) return;
    int b = blockIdx.y;
    int g = blockIdx.z;

    float2 rl  = __ldg((const float2*)rho_logit + f2);
    float rho0 = sigmoidf_(rl.x), rho1 = sigmoidf_(rl.y);
    float om0  = 1.0f - rho0,     om1  = 1.0f - rho1;

    size_t base = ((size_t)b * (size_t)S + (size_t)g * (size_t)L) * (size_t)F
                + (size_t)(f2 << 1);
    const float2* pr  = (const float2*)(fr + base);
    const float2* pim = (const float2*)(fi + base);
    size_t st = (size_t)F2;              // float2 stride per step

    float C0 = 0.0f, C1 = 0.0f;
    float2 lxr = make_float2(0.f, 0.f), lxi = make_float2(0.f, 0.f);

    int nch = L / UNR;
    float2 cr[UNR], ci[UNR];
#pragma unroll
    for (int k = 0; k < UNR; ++k) {
        cr[k] = __ldcs(pr  + (size_t)k * st);
        ci[k] = __ldcs(pim + (size_t)k * st);
    }
    pr  += (size_t)UNR * st;
    pim += (size_t)UNR * st;

#pragma unroll 1
    for (int j = 0; j < nch; ++j) {
        float2 nr[UNR], ni[UNR];
        if (j + 1 < nch) {
#pragma unroll
            for (int k = 0; k < UNR; ++k) {
                nr[k] = __ldcs(pr  + (size_t)k * st);
                ni[k] = __ldcs(pim + (size_t)k * st);
            }
            pr  += (size_t)UNR * st;
            pim += (size_t)UNR * st;
        }
#pragma unroll
        for (int k = 0; k < UNR; ++k) {
            float x2a = fmaf(cr[k].x, cr[k].x, ci[k].x * ci[k].x);
            float x2b = fmaf(cr[k].y, cr[k].y, ci[k].y * ci[k].y);
            float wa = sqrtf(fmaxf(x2a, 1e-37f));
            float wb = sqrtf(fmaxf(x2b, 1e-37f));
            C0 = fmaf(rho0, C0, om0 * wa);
            C1 = fmaf(rho1, C1, om1 * wb);
            lxr = cr[k]; lxi = ci[k];
        }
#pragma unroll
        for (int k = 0; k < UNR; ++k) { cr[k] = nr[k]; ci[k] = ni[k]; }
    }

    size_t bf0 = (size_t)b * (size_t)F + (size_t)(f2 << 1);
    float2* cdst = (float2*)(g_C + (size_t)g * MAX_BF + bf0);
    *cdst = make_float2(C0, C1);
    if (g == G - 1) {
        g_lx[bf0]     = make_float2(lxr.x, lxi.x);
        g_lx[bf0 + 1] = make_float2(lxr.y, lxi.y);
    }
}

// ---------------- Phase 2 ----------------
__global__ __launch_bounds__(256)
void phase2_kernel(const float* __restrict__ fr, const float* __restrict__ fi,
                   const float* __restrict__ ir, const float* __restrict__ ii,
                   const float* __restrict__ rho_logit,
                   const float* __restrict__ theta_raw,
                   float2* __restrict__ out, int S, int F, int L)
{
    int F2 = F >> 1;
    int total2 = gridDim.y * F2;   // gridDim.y == B
    int idx = blockIdx.x * blockDim.x + threadIdx.x;
    int b   = blockIdx.y;
    int f2  = idx;
    if (f2 >= F2) return;
    (void)total2;

    int f0 = f2 << 1;
    size_t bf0 = (size_t)b * (size_t)F + (size_t)f0;

    float2 rl = __ldg((const float2*)rho_logit + f2);
    float2 tw = __ldg((const float2*)theta_raw + f2);
    float rho0 = sigmoidf_(rl.x), rho1 = sigmoidf_(rl.y);

    float2 sr = __ldg((const float2*)(ir + bf0 - f0) + f2);   // ir[b*F + f0..]
    float2 si = __ldg((const float2*)(ii + bf0 - f0) + f2);
    float m0 = sqrtf(fmaxf(fmaf(sr.x, sr.x, si.x * si.x), 1e-37f));
    float m1 = sqrtf(fmaxf(fmaf(sr.y, sr.y, si.y * si.y), 1e-37f));

    bool complex_a = (tw.x != 0.0f) || (tw.y != 0.0f);

    if (!complex_a) {
        float D0 = powf(rho0, (float)L);
        float D1 = powf(rho1, (float)L);
#pragma unroll
        for (int g = 0; g < G; ++g) {
            const float2* c = (const float2*)(g_C + (size_t)g * MAX_BF + bf0);
            float2 cv = *c;
            m0 = fmaf(D0, m0, cv.x);
            m1 = fmaf(D1, m1, cv.y);
        }
        float2 lx0 = g_lx[bf0];
        float2 lx1 = g_lx[bf0 + 1];
        float w0 = sqrtf(fmaxf(fmaf(lx0.x, lx0.x, lx0.y * lx0.y), 1e-37f));
        float w1 = sqrtf(fmaxf(fmaf(lx1.x, lx1.x, lx1.y * lx1.y), 1e-37f));
        float s0 = m0 * __frcp_rn(w0);
        float s1 = m1 * __frcp_rn(w1);
        out[bf0]     = make_float2(lx0.x * s0, lx0.y * s0);
        out[bf0 + 1] = make_float2(lx1.x * s1, lx1.y * s1);
    } else {
        // general complex-a path (not taken for this dataset): full rescan
#pragma unroll 1
        for (int q = 0; q < 2; ++q) {
            int f = f0 + q;
            float rho = (q == 0) ? rho0 : rho1;
            float th  = 3.14159265358979323846f * tanhf(q == 0 ? tw.x : tw.y);
            float ss, sc;
            sincosf(th, &ss, &sc);
            float ar = rho * sc, ai = rho * ss, omr = 1.0f - rho;
            float m  = (q == 0) ? m0 : m1;
            const float* p  = fr + (size_t)b * (size_t)S * (size_t)F + f;
            const float* pi = fi + (size_t)b * (size_t)S * (size_t)F + f;
            float zr = 0.f, zi = 0.f, rinv = 1.f, lr = 0.f, li = 0.f;
            for (int s = 0; s < S; ++s) {
                float xr = __ldcs(p), xi = __ldcs(pi);
                p += F; pi += F;
                float x2 = fmaxf(fmaf(xr, xr, xi * xi), 1e-37f);
                float rv = rsqrtf(x2);
                float w  = x2 * rv;
                zr = fmaf(ar, m, omr * w);
                zi = ai * m;
                float z2 = fmaxf(fmaf(zr, zr, zi * zi), 1e-37f);
                m = z2 * rsqrtf(z2);
                rinv = rv; lr = xr; li = xi;
            }
            out[(size_t)b * F + f] =
                make_float2((zr * lr - zi * li) * rinv,
                            fmaf(zr, li, zi * lr) * rinv);
        }
    }
}

// ---------------- Monolithic fallback (unexpected shapes) ----------------
__global__ __launch_bounds__(256)
void mono_kernel(const float* __restrict__ fr, const float* __restrict__ fi,
                 const float* __restrict__ ir, const float* __restrict__ ii,
                 const float* __restrict__ rho_logit,
                 const float* __restrict__ theta_raw,
                 float2* __restrict__ out, int S, int F)
{
    int f = blockIdx.x * blockDim.x + threadIdx.x;
    if (f >= F) return;
    int b = blockIdx.y;
    size_t bf = (size_t)b * (size_t)F + (size_t)f;

    float rho = sigmoidf_(rho_logit[f]);
    float th  = 3.14159265358979323846f * tanhf(theta_raw[f]);
    float ss, sc;
    sincosf(th, &ss, &sc);
    float ar = rho * sc, ai = rho * ss, omr = 1.0f - rho;

    float srv = ir[bf], siv = ii[bf];
    float m = sqrtf(fmaxf(fmaf(srv, srv, siv * siv), 1e-37f));

    const float* pr  = fr + (size_t)b * (size_t)S * (size_t)F + f;
    const float* pim = fi + (size_t)b * (size_t)S * (size_t)F + f;
    float zr = 0.f, zi = 0.f, rinv = 1.f, lxr = 0.f, lxi = 0.f;
    for (int s = 0; s < S; ++s) {
        float xr = __ldcs(pr), xi = __ldcs(pim);
        pr += F; pim += F;
        float x2 = fmaxf(fmaf(xr, xr, xi * xi), 1e-37f);
        float rv = rsqrtf(x2);
        float w  = x2 * rv;
        zr = fmaf(ar, m, omr * w);
        zi = ai * m;
        float z2 = fmaxf(fmaf(zr, zr, zi * zi), 1e-37f);
        m = z2 * rsqrtf(z2);
        rinv = rv; lxr = xr; lxi = xi;
    }
    out[bf] = make_float2((zr * lxr - zi * lxi) * rinv,
                          fmaf(zr, lxi, zi * lxr) * rinv);
}

extern "C" void kernel_launch(void* const* d_in, const int* in_sizes, int n_in,
                              void* d_out, int out_size)
{
    const float* fr = (const float*)d_in[0];
    const float* fi = (const float*)d_in[1];
    const float* ir = (const float*)d_in[2];
    const float* ii = (const float*)d_in[3];
    const float* rl = (const float*)d_in[4];
    const float* tr = (const float*)d_in[5];

    int F  = in_sizes[4];
    int BF = in_sizes[2];
    int B  = BF / F;
    int S  = in_sizes[0] / BF;

    dim3 block(256);

    bool fast = (BF <= MAX_BF) && (F % 512 == 0) && (S % (G * UNR) == 0);
    if (fast) {
        int L  = S / G;
        int F2 = F / 2;
        dim3 grid1((F2 + 255) / 256, B, G);
        phase1_kernel<<<grid1, block>>>(fr, fi, rl, S, F, L);
        dim3 grid2((F2 + 255) / 256, B);
        phase2_kernel<<<grid2, block>>>(fr, fi, ir, ii, rl, tr,
                                        (float2*)d_out, S, F, L);
    } else {
        dim3 grid((F + 255) / 256, B);
        mono_kernel<<<grid, block>>>(fr, fi, ir, ii, rl, tr,
                                     (float2*)d_out, S, F);
    }
}